// round 6
// baseline (speedup 1.0000x reference)
#include <cuda_runtime.h>
#include <cuda_fp16.h>
#include <math.h>
#include <stdint.h>

#define BATCH 16
#define NQ    64
#define NSEQ  4096
#define DH    128
#define SCALE 0.08838834764831845f   // 1/sqrt(128)

// Scratch
__device__ float g_attn[(size_t)BATCH * NQ * NSEQ];   // softmax weights
__device__ float g_vout[(size_t)BATCH * NQ * DH];     // sum_n a V  (exact fp32)
__device__ float g_wk  [(size_t)BATCH * NQ * DH];     // sum_n a K  (exact fp32)

// ---------------------------------------------------------------------------
// Kernel 1: scores S[b,q,n] = (Q[b,q,:] . K[b,n,:]) * SCALE
// ---------------------------------------------------------------------------
__global__ void scores_kernel(const float* __restrict__ Q,
                              const float* __restrict__ K) {
    __shared__ float Qs[64][33];
    __shared__ float Kt[128][33];

    const int b   = blockIdx.y;
    const int nt  = blockIdx.x;
    const int tid = threadIdx.x;
    const int ty  = tid >> 5;
    const int tx  = tid & 31;

    const float* Qb = Q + (size_t)b * NQ * DH;
    const float* Kb = K + ((size_t)b * NSEQ + (size_t)nt * 128) * DH;

    float acc[8][4];
    #pragma unroll
    for (int i = 0; i < 8; i++)
        #pragma unroll
        for (int j = 0; j < 4; j++) acc[i][j] = 0.f;

    for (int d0 = 0; d0 < DH; d0 += 32) {
        for (int i = tid; i < 64 * 32; i += 256) {
            int r = i >> 5, c = i & 31;
            Qs[r][c] = Qb[r * DH + d0 + c];
        }
        for (int i = tid; i < 128 * 32; i += 256) {
            int r = i >> 5, c = i & 31;
            Kt[r][c] = Kb[r * DH + d0 + c];
        }
        __syncthreads();

        #pragma unroll 8
        for (int dd = 0; dd < 32; dd++) {
            float qf[8], kf[4];
            #pragma unroll
            for (int i = 0; i < 8; i++) qf[i] = Qs[ty * 8 + i][dd];
            #pragma unroll
            for (int j = 0; j < 4; j++) kf[j] = Kt[tx * 4 + j][dd];
            #pragma unroll
            for (int i = 0; i < 8; i++)
                #pragma unroll
                for (int j = 0; j < 4; j++)
                    acc[i][j] += qf[i] * kf[j];
        }
        __syncthreads();
    }

    float* S = g_attn + ((size_t)b * NQ) * NSEQ + (size_t)nt * 128;
    #pragma unroll
    for (int i = 0; i < 8; i++)
        #pragma unroll
        for (int j = 0; j < 4; j++)
            S[(size_t)(ty * 8 + i) * NSEQ + tx * 4 + j] = acc[i][j] * SCALE;
}

// ---------------------------------------------------------------------------
// Kernel 2: in-place softmax, shfl reductions, float4 I/O.
// ---------------------------------------------------------------------------
__global__ void softmax_kernel() {
    const int row = blockIdx.x;
    float4* p = (float4*)(g_attn + (size_t)row * NSEQ);
    const int tid  = threadIdx.x;
    const int lane = tid & 31;
    const int wid  = tid >> 5;
    __shared__ float red[8];

    float4 v[4];
    float m = -1e30f;
    #pragma unroll
    for (int i = 0; i < 4; i++) {
        v[i] = p[tid + i * 256];
        m = fmaxf(m, fmaxf(fmaxf(v[i].x, v[i].y), fmaxf(v[i].z, v[i].w)));
    }
    #pragma unroll
    for (int s = 16; s > 0; s >>= 1)
        m = fmaxf(m, __shfl_xor_sync(0xffffffffu, m, s));
    if (lane == 0) red[wid] = m;
    __syncthreads();
    if (wid == 0) {
        float t = red[lane & 7];
        #pragma unroll
        for (int s = 4; s > 0; s >>= 1)
            t = fmaxf(t, __shfl_xor_sync(0xffffffffu, t, s));
        if (lane == 0) red[0] = t;
    }
    __syncthreads();
    m = red[0];

    float sum = 0.f;
    #pragma unroll
    for (int i = 0; i < 4; i++) {
        v[i].x = __expf(v[i].x - m); v[i].y = __expf(v[i].y - m);
        v[i].z = __expf(v[i].z - m); v[i].w = __expf(v[i].w - m);
        sum += (v[i].x + v[i].y) + (v[i].z + v[i].w);
    }
    #pragma unroll
    for (int s = 16; s > 0; s >>= 1)
        sum += __shfl_xor_sync(0xffffffffu, sum, s);
    if (lane == 0) red[wid] = sum;
    __syncthreads();
    if (wid == 0) {
        float t = red[lane & 7];
        #pragma unroll
        for (int s = 4; s > 0; s >>= 1)
            t += __shfl_xor_sync(0xffffffffu, t, s);
        if (lane == 0) red[0] = t;
    }
    __syncthreads();
    const float inv = 1.0f / red[0];

    #pragma unroll
    for (int i = 0; i < 4; i++) {
        v[i].x *= inv; v[i].y *= inv; v[i].z *= inv; v[i].w *= inv;
        p[tid + i * 256] = v[i];
    }
}

// ---------------------------------------------------------------------------
// Kernel 3: aux — exact fp32 vout = a.V, wk = a.K. 16 q's per CTA.
// grid 128 = (b:16, mat:2, qg:4).
// ---------------------------------------------------------------------------
__global__ __launch_bounds__(256) void aux_kernel(const float* __restrict__ K,
                                                  const float* __restrict__ V) {
    __shared__ float Ms[64 * 128];   // 32KB
    __shared__ float As[16 * 64];    //  4KB

    const int bid = blockIdx.x;
    const int b   = bid >> 3;
    const int rm  = bid & 7;
    const int mat = rm >> 2;
    const int qg  = rm & 3;
    const int bq0 = b * NQ + qg * 16;

    const float* M  = (mat ? K : V) + (size_t)b * NSEQ * DH;
    const float* aA = g_attn + (size_t)bq0 * NSEQ;

    const int tid  = threadIdx.x;
    const int ccol = tid & 127;
    const int qh   = tid >> 7;   // 0..1 -> 8 q's each

    float acc[8];
    #pragma unroll
    for (int i = 0; i < 8; i++) acc[i] = 0.f;

    for (int n0 = 0; n0 < NSEQ; n0 += 64) {
        const float4* Mg  = (const float4*)(M + (size_t)n0 * DH);
        float4*       Ms4 = (float4*)Ms;
        #pragma unroll
        for (int i = 0; i < 8; i++) Ms4[tid + i * 256] = Mg[tid + i * 256];
        #pragma unroll
        for (int i = 0; i < 4; i++) {
            int idx = tid + i * 256;
            int q = idx >> 6, n = idx & 63;
            As[idx] = aA[(size_t)q * NSEQ + n0 + n];
        }
        __syncthreads();

        #pragma unroll 4
        for (int n = 0; n < 64; n++) {
            float mv = Ms[n * 128 + ccol];
            #pragma unroll
            for (int i = 0; i < 8; i++)
                acc[i] += As[(qh * 8 + i) * 64 + n] * mv;
        }
        __syncthreads();
    }

    float* dst = mat ? g_wk : g_vout;
    #pragma unroll
    for (int i = 0; i < 8; i++)
        dst[(size_t)(bq0 + qh * 8 + i) * DH + ccol] = acc[i];
}

// ---------------------------------------------------------------------------
// Kernel 4: jac — per CTA (4 q, 64 v, 128 k), 512 threads / 16 warps (4wm x 4wn).
//   C_q[v,k] = sum_n (a_qn V[n,v]) K[n,k]   (fp16 MMA, fp32 acc)
//   J_q      = SCALE * (C_q - vout_q (x) wk_q)
// ---------------------------------------------------------------------------
#define KC     32
#define AVS    72    // halves per aV row  (64 + 8 pad)
#define KSS    136   // halves per K row   (128 + 8 pad)

__device__ __forceinline__ void mma_f16(float c[4], uint32_t a0, uint32_t a1,
                                        uint32_t a2, uint32_t a3,
                                        uint32_t b0, uint32_t b1) {
    asm volatile(
        "mma.sync.aligned.m16n8k16.row.col.f32.f16.f16.f32 "
        "{%0,%1,%2,%3}, {%4,%5,%6,%7}, {%8,%9}, {%0,%1,%2,%3};"
        : "+f"(c[0]), "+f"(c[1]), "+f"(c[2]), "+f"(c[3])
        : "r"(a0), "r"(a1), "r"(a2), "r"(a3), "r"(b0), "r"(b1));
}

__device__ __forceinline__ void ldsm4t(uint32_t& r0, uint32_t& r1,
                                       uint32_t& r2, uint32_t& r3, uint32_t addr) {
    asm volatile(
        "ldmatrix.sync.aligned.m8n8.x4.trans.shared.b16 {%0,%1,%2,%3}, [%4];"
        : "=r"(r0), "=r"(r1), "=r"(r2), "=r"(r3) : "r"(addr));
}

__global__ __launch_bounds__(512, 1) void jac_kernel(const float* __restrict__ K,
                                                     const float* __restrict__ V,
                                                     float* __restrict__ out) {
    __shared__ __half avs[4][KC * AVS];   // 18432 B
    __shared__ __half kss[KC * KSS];      //  8704 B

    const int bid = blockIdx.x;           // 512 CTAs
    const int b   = bid >> 5;
    const int r   = bid & 31;
    const int qg  = r >> 1;               // 0..15 -> 4 q's
    const int vh  = r & 1;                // 0..1  -> 64 v-cols
    const int v0  = vh * 64;
    const int bq0 = b * NQ + qg * 4;

    const float* aA = g_attn + (size_t)bq0 * NSEQ;
    const float* Vb = V + (size_t)b * NSEQ * DH + v0;
    const float* Kb = K + (size_t)b * NSEQ * DH;

    const int tid  = threadIdx.x;
    const int warp = tid >> 5;
    const int lane = tid & 31;

    // load-phase indices (512 threads)
    const int rowV  = tid >> 4;    // 0..31, 1 float4 each
    const int colV4 = tid & 15;
    const int rowK  = tid >> 5;    // 0..15, rows rowK, rowK+16
    const int colK4 = tid & 31;

    // mma-phase indices
    const int g  = lane >> 2;
    const int t  = lane & 3;
    const int lj = lane & 7;
    const int ls = lane >> 3;
    const int wm = warp >> 2;      // 0..3 -> m0 = wm*16 (of 64 v)
    const int wn = warp & 3;       // 0..3 -> k cols wn*32..+32
    const int m0 = wm * 16;

    const uint32_t avs_base = (uint32_t)__cvta_generic_to_shared(avs);
    const uint32_t kss_base = (uint32_t)__cvta_generic_to_shared(kss);
    const uint32_t a_lane =
        (uint32_t)(((lj + ((ls >> 1) << 3)) * AVS + m0 + ((ls & 1) << 3)) * 2);
    const uint32_t b_lane =
        (uint32_t)(((lj + ((ls & 1) << 3)) * KSS + wn * 32 + ((ls >> 1) << 3)) * 2);

    float C[4][4][4];
    #pragma unroll
    for (int q = 0; q < 4; q++)
        #pragma unroll
        for (int nt = 0; nt < 4; nt++)
            #pragma unroll
            for (int i = 0; i < 4; i++) C[q][nt][i] = 0.f;

    // prologue: chunk 0 into regs
    float4 va, kk[2];
    float  ar[4];
    va = *(const float4*)(Vb + (size_t)rowV * DH + colV4 * 4);
    #pragma unroll
    for (int i = 0; i < 2; i++)
        kk[i] = *(const float4*)(Kb + (size_t)(rowK + 16 * i) * DH + colK4 * 4);
    #pragma unroll
    for (int q = 0; q < 4; q++)
        ar[q] = aA[(size_t)q * NSEQ + rowV];

    for (int c = 0; c < NSEQ / KC; c++) {
        // ---- build tiles from current regs
        #pragma unroll
        for (int i = 0; i < 2; i++) {
            __half2 p0 = __floats2half2_rn(kk[i].x, kk[i].y);
            __half2 p1 = __floats2half2_rn(kk[i].z, kk[i].w);
            uint2 pk;
            pk.x = *(uint32_t*)&p0; pk.y = *(uint32_t*)&p1;
            *(uint2*)&kss[(rowK + 16 * i) * KSS + colK4 * 4] = pk;
        }
        #pragma unroll
        for (int q = 0; q < 4; q++) {
            const float aq = ar[q];
            __half2 h0 = __floats2half2_rn(aq * va.x, aq * va.y);
            __half2 h1 = __floats2half2_rn(aq * va.z, aq * va.w);
            uint2 u;
            u.x = *(uint32_t*)&h0; u.y = *(uint32_t*)&h1;
            *(uint2*)&avs[q][rowV * AVS + colV4 * 4] = u;
        }
        __syncthreads();   // tiles ready

        // ---- prefetch next chunk into regs (overlaps with MMA)
        float4 nva, nkk[2];
        float  nar[4];
        if (c + 1 < NSEQ / KC) {
            const size_t nn = (size_t)(c + 1) * KC;
            nva = *(const float4*)(Vb + (nn + rowV) * DH + colV4 * 4);
            #pragma unroll
            for (int i = 0; i < 2; i++)
                nkk[i] = *(const float4*)(Kb + (nn + rowK + 16 * i) * DH + colK4 * 4);
            #pragma unroll
            for (int q = 0; q < 4; q++)
                nar[q] = aA[(size_t)q * NSEQ + nn + rowV];
        }

        // ---- MMA: 2 ksteps of 16
        #pragma unroll
        for (int ks = 0; ks < 2; ks++) {
            uint32_t bf[4][2];
            #pragma unroll
            for (int p = 0; p < 2; p++) {
                ldsm4t(bf[2 * p][0], bf[2 * p][1],
                       bf[2 * p + 1][0], bf[2 * p + 1][1],
                       kss_base + b_lane + p * 32 + ks * (16 * KSS * 2));
            }
            #pragma unroll
            for (int q = 0; q < 4; q++) {
                uint32_t a0, a1, a2, a3;
                ldsm4t(a0, a1, a2, a3,
                       avs_base + q * (KC * AVS * 2) + a_lane + ks * (16 * AVS * 2));
                #pragma unroll
                for (int nt = 0; nt < 4; nt++)
                    mma_f16(C[q][nt], a0, a1, a2, a3, bf[nt][0], bf[nt][1]);
            }
        }

        va = nva;
        kk[0] = nkk[0]; kk[1] = nkk[1];
        #pragma unroll
        for (int q = 0; q < 4; q++) ar[q] = nar[q];
        __syncthreads();   // MMA reads done before next writes
    }

    // ---- epilogue: J = SCALE * (C - vout (x) wk)
    #pragma unroll
    for (int q = 0; q < 4; q++) {
        const int bq = bq0 + q;
        const float* vo = g_vout + (size_t)bq * DH + v0;
        const float* wq = g_wk   + (size_t)bq * DH;
        float* o = out + (size_t)bq * DH * DH;
        const float vo0 = vo[m0 + g];
        const float vo1 = vo[m0 + g + 8];
        #pragma unroll
        for (int nt = 0; nt < 4; nt++) {
            const int col = wn * 32 + nt * 8 + 2 * t;
            const float w0 = wq[col];
            const float w1 = wq[col + 1];
            float2 r0, r1;
            r0.x = SCALE * (C[q][nt][0] - vo0 * w0);
            r0.y = SCALE * (C[q][nt][1] - vo0 * w1);
            r1.x = SCALE * (C[q][nt][2] - vo1 * w0);
            r1.y = SCALE * (C[q][nt][3] - vo1 * w1);
            *(float2*)&o[(size_t)(v0 + m0 + g) * DH + col]     = r0;
            *(float2*)&o[(size_t)(v0 + m0 + g + 8) * DH + col] = r1;
        }
    }
}

// ---------------------------------------------------------------------------
extern "C" void kernel_launch(void* const* d_in, const int* in_sizes, int n_in,
                              void* d_out, int out_size) {
    const float* Q = (const float*)d_in[0];
    const float* K = (const float*)d_in[1];
    const float* V = (const float*)d_in[2];
    float* out = (float*)d_out;

    scores_kernel<<<dim3(32, BATCH), 256>>>(Q, K);
    softmax_kernel<<<BATCH * NQ, 256>>>();
    aux_kernel<<<128, 256>>>(K, V);
    jac_kernel<<<BATCH * NQ / 2, 512>>>(K, V, out);
}

// round 7
// speedup vs baseline: 1.1927x; 1.1927x over previous
#include <cuda_runtime.h>
#include <cuda_fp16.h>
#include <math.h>
#include <stdint.h>

#define BATCH 16
#define NQ    64
#define NSEQ  4096
#define DH    128
#define SCALE 0.08838834764831845f   // 1/sqrt(128)

// Scratch
__device__ float  g_attn[(size_t)BATCH * NQ * NSEQ];   // softmax weights
__device__ float  g_vout[(size_t)BATCH * NQ * DH];     // sum_n a V  (exact fp32)
__device__ float  g_wk  [(size_t)BATCH * NQ * DH];     // sum_n a K  (exact fp32)
__device__ __half g_Kh  [(size_t)BATCH * NSEQ * DH];   // K pre-rounded to fp16

// ---------------------------------------------------------------------------
// Kernel 0: prep — Kh = fp16(K), same rounding as the old in-kernel convert.
// ---------------------------------------------------------------------------
__global__ void prep_kernel(const float* __restrict__ K) {
    const size_t i = ((size_t)blockIdx.x * 256 + threadIdx.x) * 4;
    float4 v = *(const float4*)(K + i);
    __half2 h0 = __floats2half2_rn(v.x, v.y);
    __half2 h1 = __floats2half2_rn(v.z, v.w);
    uint2 u;
    u.x = *(uint32_t*)&h0;
    u.y = *(uint32_t*)&h1;
    *(uint2*)&g_Kh[i] = u;
}

// ---------------------------------------------------------------------------
// Kernel 1: scores S[b,q,n] = (Q[b,q,:] . K[b,n,:]) * SCALE
// ---------------------------------------------------------------------------
__global__ void scores_kernel(const float* __restrict__ Q,
                              const float* __restrict__ K) {
    __shared__ float Qs[64][33];
    __shared__ float Kt[128][33];

    const int b   = blockIdx.y;
    const int nt  = blockIdx.x;
    const int tid = threadIdx.x;
    const int ty  = tid >> 5;
    const int tx  = tid & 31;

    const float* Qb = Q + (size_t)b * NQ * DH;
    const float* Kb = K + ((size_t)b * NSEQ + (size_t)nt * 128) * DH;

    float acc[8][4];
    #pragma unroll
    for (int i = 0; i < 8; i++)
        #pragma unroll
        for (int j = 0; j < 4; j++) acc[i][j] = 0.f;

    for (int d0 = 0; d0 < DH; d0 += 32) {
        for (int i = tid; i < 64 * 32; i += 256) {
            int r = i >> 5, c = i & 31;
            Qs[r][c] = Qb[r * DH + d0 + c];
        }
        for (int i = tid; i < 128 * 32; i += 256) {
            int r = i >> 5, c = i & 31;
            Kt[r][c] = Kb[r * DH + d0 + c];
        }
        __syncthreads();

        #pragma unroll 8
        for (int dd = 0; dd < 32; dd++) {
            float qf[8], kf[4];
            #pragma unroll
            for (int i = 0; i < 8; i++) qf[i] = Qs[ty * 8 + i][dd];
            #pragma unroll
            for (int j = 0; j < 4; j++) kf[j] = Kt[tx * 4 + j][dd];
            #pragma unroll
            for (int i = 0; i < 8; i++)
                #pragma unroll
                for (int j = 0; j < 4; j++)
                    acc[i][j] += qf[i] * kf[j];
        }
        __syncthreads();
    }

    float* S = g_attn + ((size_t)b * NQ) * NSEQ + (size_t)nt * 128;
    #pragma unroll
    for (int i = 0; i < 8; i++)
        #pragma unroll
        for (int j = 0; j < 4; j++)
            S[(size_t)(ty * 8 + i) * NSEQ + tx * 4 + j] = acc[i][j] * SCALE;
}

// ---------------------------------------------------------------------------
// Kernel 2: in-place softmax, shfl reductions, float4 I/O.
// ---------------------------------------------------------------------------
__global__ void softmax_kernel() {
    const int row = blockIdx.x;
    float4* p = (float4*)(g_attn + (size_t)row * NSEQ);
    const int tid  = threadIdx.x;
    const int lane = tid & 31;
    const int wid  = tid >> 5;
    __shared__ float red[8];

    float4 v[4];
    float m = -1e30f;
    #pragma unroll
    for (int i = 0; i < 4; i++) {
        v[i] = p[tid + i * 256];
        m = fmaxf(m, fmaxf(fmaxf(v[i].x, v[i].y), fmaxf(v[i].z, v[i].w)));
    }
    #pragma unroll
    for (int s = 16; s > 0; s >>= 1)
        m = fmaxf(m, __shfl_xor_sync(0xffffffffu, m, s));
    if (lane == 0) red[wid] = m;
    __syncthreads();
    if (wid == 0) {
        float t = red[lane & 7];
        #pragma unroll
        for (int s = 4; s > 0; s >>= 1)
            t = fmaxf(t, __shfl_xor_sync(0xffffffffu, t, s));
        if (lane == 0) red[0] = t;
    }
    __syncthreads();
    m = red[0];

    float sum = 0.f;
    #pragma unroll
    for (int i = 0; i < 4; i++) {
        v[i].x = __expf(v[i].x - m); v[i].y = __expf(v[i].y - m);
        v[i].z = __expf(v[i].z - m); v[i].w = __expf(v[i].w - m);
        sum += (v[i].x + v[i].y) + (v[i].z + v[i].w);
    }
    #pragma unroll
    for (int s = 16; s > 0; s >>= 1)
        sum += __shfl_xor_sync(0xffffffffu, sum, s);
    if (lane == 0) red[wid] = sum;
    __syncthreads();
    if (wid == 0) {
        float t = red[lane & 7];
        #pragma unroll
        for (int s = 4; s > 0; s >>= 1)
            t += __shfl_xor_sync(0xffffffffu, t, s);
        if (lane == 0) red[0] = t;
    }
    __syncthreads();
    const float inv = 1.0f / red[0];

    #pragma unroll
    for (int i = 0; i < 4; i++) {
        v[i].x *= inv; v[i].y *= inv; v[i].z *= inv; v[i].w *= inv;
        p[tid + i * 256] = v[i];
    }
}

// ---------------------------------------------------------------------------
// Kernel 3: aux — exact fp32 vout = a.V, wk = a.K (R5 version, 8 q / CTA).
// grid 256 = (b:16, mat:2, qg:8).
// ---------------------------------------------------------------------------
__global__ __launch_bounds__(256) void aux_kernel(const float* __restrict__ K,
                                                  const float* __restrict__ V) {
    __shared__ float Ms[64 * 128];   // 32KB
    __shared__ float As[8 * 64];

    const int bid = blockIdx.x;
    const int b   = bid >> 4;
    const int rm  = bid & 15;
    const int mat = rm >> 3;
    const int qg  = rm & 7;
    const int bq0 = b * NQ + qg * 8;

    const float* M  = (mat ? K : V) + (size_t)b * NSEQ * DH;
    const float* aA = g_attn + (size_t)bq0 * NSEQ;

    const int tid  = threadIdx.x;
    const int ccol = tid & 127;
    const int qh   = tid >> 7;   // 0..1 -> 4 q's each

    float acc[4] = {0.f, 0.f, 0.f, 0.f};

    for (int n0 = 0; n0 < NSEQ; n0 += 64) {
        const float4* Mg  = (const float4*)(M + (size_t)n0 * DH);
        float4*       Ms4 = (float4*)Ms;
        #pragma unroll
        for (int i = 0; i < 8; i++) Ms4[tid + i * 256] = Mg[tid + i * 256];
        #pragma unroll
        for (int i = 0; i < 2; i++) {
            int idx = tid + i * 256;
            int q = idx >> 6, n = idx & 63;
            As[idx] = aA[(size_t)q * NSEQ + n0 + n];
        }
        __syncthreads();

        #pragma unroll 4
        for (int n = 0; n < 64; n++) {
            float mv = Ms[n * 128 + ccol];
            #pragma unroll
            for (int i = 0; i < 4; i++)
                acc[i] += As[(qh * 4 + i) * 64 + n] * mv;
        }
        __syncthreads();
    }

    float* dst = mat ? g_wk : g_vout;
    #pragma unroll
    for (int i = 0; i < 4; i++)
        dst[(size_t)(bq0 + qh * 4 + i) * DH + ccol] = acc[i];
}

// ---------------------------------------------------------------------------
// Kernel 4: jac — per CTA (4 q, 64 v, 128 k), 512 thr / 16 warps (4wm x 4wn).
// KC=64, double-buffered smem (1 barrier/chunk), K tile via cp.async of
// pre-converted fp16 K. C_q = sum_n (a_qn V[n,v]) K[n,k]; J = SCALE*(C - vo wk).
// ---------------------------------------------------------------------------
#define KC     64
#define AVS    72      // halves per aV row  (64 + 8 pad)
#define KSS    136     // halves per K row   (128 + 8 pad)
#define BUFH   (4 * KC * AVS + KC * KSS)          // 27136 halves per buffer
#define JAC_SMEM (2 * BUFH * 2)                   // 108544 bytes

__device__ __forceinline__ void mma_f16(float c[4], uint32_t a0, uint32_t a1,
                                        uint32_t a2, uint32_t a3,
                                        uint32_t b0, uint32_t b1) {
    asm volatile(
        "mma.sync.aligned.m16n8k16.row.col.f32.f16.f16.f32 "
        "{%0,%1,%2,%3}, {%4,%5,%6,%7}, {%8,%9}, {%0,%1,%2,%3};"
        : "+f"(c[0]), "+f"(c[1]), "+f"(c[2]), "+f"(c[3])
        : "r"(a0), "r"(a1), "r"(a2), "r"(a3), "r"(b0), "r"(b1));
}

__device__ __forceinline__ void ldsm4t(uint32_t& r0, uint32_t& r1,
                                       uint32_t& r2, uint32_t& r3, uint32_t addr) {
    asm volatile(
        "ldmatrix.sync.aligned.m8n8.x4.trans.shared.b16 {%0,%1,%2,%3}, [%4];"
        : "=r"(r0), "=r"(r1), "=r"(r2), "=r"(r3) : "r"(addr));
}

__device__ __forceinline__ void cp16(uint32_t dst, const void* src) {
    asm volatile("cp.async.cg.shared.global [%0], [%1], 16;"
                 :: "r"(dst), "l"(src));
}

__global__ __launch_bounds__(512, 1) void jac_kernel(const float* __restrict__ V,
                                                     float* __restrict__ out) {
    extern __shared__ __half sm[];

    const int bid = blockIdx.x;           // 512 CTAs
    const int b   = bid >> 5;
    const int r   = bid & 31;
    const int qg  = r >> 1;               // 0..15 -> 4 q's
    const int vh  = r & 1;                // 0..1  -> 64 v-cols
    const int v0  = vh * 64;
    const int bq0 = b * NQ + qg * 4;

    const float*  aA  = g_attn + (size_t)bq0 * NSEQ;
    const float*  Vb  = V + (size_t)b * NSEQ * DH + v0;
    const __half* Khb = g_Kh + (size_t)b * NSEQ * DH;

    const int tid  = threadIdx.x;
    const int warp = tid >> 5;
    const int lane = tid & 31;

    // load-phase indices
    const int rowV  = tid >> 4;    // 0..31 ; rows rowV, rowV+32
    const int colV4 = tid & 15;
    const int rowK  = tid >> 3;    // 0..63
    const int segK  = tid & 7;     // 16B segs segK, segK+8

    // mma-phase indices
    const int g  = lane >> 2;
    const int t  = lane & 3;
    const int lj = lane & 7;
    const int ls = lane >> 3;
    const int wm = warp >> 2;      // 0..3 -> m0 = wm*16 (of 64 v)
    const int wn = warp & 3;       // 0..3 -> k cols wn*32..+32
    const int m0 = wm * 16;

    const uint32_t sm_u = (uint32_t)__cvta_generic_to_shared(sm);
    const uint32_t a_lane =
        (uint32_t)(((lj + ((ls >> 1) << 3)) * AVS + m0 + ((ls & 1) << 3)) * 2);
    const uint32_t b_lane =
        (uint32_t)(((lj + ((ls & 1) << 3)) * KSS + wn * 32 + ((ls >> 1) << 3)) * 2);

    float C[4][4][4];
    #pragma unroll
    for (int q = 0; q < 4; q++)
        #pragma unroll
        for (int nt = 0; nt < 4; nt++)
            #pragma unroll
            for (int i = 0; i < 4; i++) C[q][nt][i] = 0.f;

    float4 va[2];
    float  ar[4][2];

#define LOAD_REGS(n0_)                                                        \
    do {                                                                      \
        va[0] = *(const float4*)(Vb + ((size_t)(n0_) + rowV) * DH + colV4 * 4);\
        va[1] = *(const float4*)(Vb + ((size_t)(n0_) + rowV + 32) * DH + colV4 * 4);\
        _Pragma("unroll")                                                     \
        for (int q_ = 0; q_ < 4; q_++) {                                      \
            ar[q_][0] = aA[(size_t)q_ * NSEQ + (n0_) + rowV];                 \
            ar[q_][1] = aA[(size_t)q_ * NSEQ + (n0_) + rowV + 32];            \
        }                                                                     \
    } while (0)

#define STORE_TILES(buf_, n0_)                                                \
    do {                                                                      \
        const uint32_t kb_ = sm_u + (uint32_t)(((buf_) * BUFH + 4 * KC * AVS) * 2);\
        const __half* kg_ = Khb + ((size_t)(n0_) + rowK) * DH;                \
        cp16(kb_ + (rowK * KSS + segK * 8) * 2, kg_ + segK * 8);              \
        cp16(kb_ + (rowK * KSS + (segK + 8) * 8) * 2, kg_ + (segK + 8) * 8);  \
        asm volatile("cp.async.commit_group;");                               \
        _Pragma("unroll")                                                     \
        for (int q_ = 0; q_ < 4; q_++) {                                      \
            _Pragma("unroll")                                                 \
            for (int i_ = 0; i_ < 2; i_++) {                                  \
                const float aq_ = ar[q_][i_];                                 \
                __half2 h0_ = __floats2half2_rn(aq_ * va[i_].x, aq_ * va[i_].y);\
                __half2 h1_ = __floats2half2_rn(aq_ * va[i_].z, aq_ * va[i_].w);\
                uint2 u_;                                                     \
                u_.x = *(uint32_t*)&h0_; u_.y = *(uint32_t*)&h1_;             \
                *(uint2*)&sm[(buf_) * BUFH + q_ * (KC * AVS) +                \
                             (rowV + 32 * i_) * AVS + colV4 * 4] = u_;        \
            }                                                                 \
        }                                                                     \
    } while (0)

#define MMA_CHUNK(buf_)                                                       \
    do {                                                                      \
        _Pragma("unroll")                                                     \
        for (int ks_ = 0; ks_ < 4; ks_++) {                                   \
            uint32_t bf_[4][2];                                               \
            const uint32_t ka_ = sm_u +                                       \
                (uint32_t)(((buf_) * BUFH + 4 * KC * AVS) * 2) + b_lane +     \
                ks_ * (16 * KSS * 2);                                         \
            ldsm4t(bf_[0][0], bf_[0][1], bf_[1][0], bf_[1][1], ka_);          \
            ldsm4t(bf_[2][0], bf_[2][1], bf_[3][0], bf_[3][1], ka_ + 32);     \
            _Pragma("unroll")                                                 \
            for (int q_ = 0; q_ < 4; q_++) {                                  \
                uint32_t a0_, a1_, a2_, a3_;                                  \
                ldsm4t(a0_, a1_, a2_, a3_,                                    \
                       sm_u + (uint32_t)(((buf_) * BUFH + q_ * (KC * AVS)) * 2)\
                       + a_lane + ks_ * (16 * AVS * 2));                      \
                mma_f16(C[q_][0], a0_, a1_, a2_, a3_, bf_[0][0], bf_[0][1]);  \
                mma_f16(C[q_][1], a0_, a1_, a2_, a3_, bf_[1][0], bf_[1][1]);  \
                mma_f16(C[q_][2], a0_, a1_, a2_, a3_, bf_[2][0], bf_[2][1]);  \
                mma_f16(C[q_][3], a0_, a1_, a2_, a3_, bf_[3][0], bf_[3][1]);  \
            }                                                                 \
        }                                                                     \
    } while (0)

    const int NCH = NSEQ / KC;   // 64 (even)

    // prologue
    LOAD_REGS(0);
    STORE_TILES(0, 0);
    LOAD_REGS(KC);
    asm volatile("cp.async.wait_group 0;");
    __syncthreads();

    for (int c = 0; c < NCH; c += 2) {
        // even iteration: compute buf0, fill buf1 with chunk c+1
        if (c + 1 < NCH) STORE_TILES(1, (c + 1) * KC);
        if (c + 2 < NCH) LOAD_REGS((c + 2) * KC);
        MMA_CHUNK(0);
        asm volatile("cp.async.wait_group 0;");
        __syncthreads();

        // odd iteration: compute buf1, fill buf0 with chunk c+2
        if (c + 2 < NCH) STORE_TILES(0, (c + 2) * KC);
        if (c + 3 < NCH) LOAD_REGS((c + 3) * KC);
        MMA_CHUNK(1);
        asm volatile("cp.async.wait_group 0;");
        __syncthreads();
    }

    // ---- epilogue: J = SCALE * (C - vout (x) wk)
    #pragma unroll
    for (int q = 0; q < 4; q++) {
        const int bq = bq0 + q;
        const float* vo = g_vout + (size_t)bq * DH + v0;
        const float* wq = g_wk   + (size_t)bq * DH;
        float* o = out + (size_t)bq * DH * DH;
        const float vo0 = vo[m0 + g];
        const float vo1 = vo[m0 + g + 8];
        #pragma unroll
        for (int nt = 0; nt < 4; nt++) {
            const int col = wn * 32 + nt * 8 + 2 * t;
            const float w0 = wq[col];
            const float w1 = wq[col + 1];
            float2 r0, r1;
            r0.x = SCALE * (C[q][nt][0] - vo0 * w0);
            r0.y = SCALE * (C[q][nt][1] - vo0 * w1);
            r1.x = SCALE * (C[q][nt][2] - vo1 * w0);
            r1.y = SCALE * (C[q][nt][3] - vo1 * w1);
            *(float2*)&o[(size_t)(v0 + m0 + g) * DH + col]     = r0;
            *(float2*)&o[(size_t)(v0 + m0 + g + 8) * DH + col] = r1;
        }
    }
}

// ---------------------------------------------------------------------------
extern "C" void kernel_launch(void* const* d_in, const int* in_sizes, int n_in,
                              void* d_out, int out_size) {
    const float* Q = (const float*)d_in[0];
    const float* K = (const float*)d_in[1];
    const float* V = (const float*)d_in[2];
    float* out = (float*)d_out;

    cudaFuncSetAttribute(jac_kernel,
                         cudaFuncAttributeMaxDynamicSharedMemorySize, JAC_SMEM);

    prep_kernel<<<(BATCH * NSEQ * DH) / (256 * 4), 256>>>(K);
    scores_kernel<<<dim3(32, BATCH), 256>>>(Q, K);
    softmax_kernel<<<BATCH * NQ, 256>>>();
    aux_kernel<<<256, 256>>>(K, V);
    jac_kernel<<<BATCH * NQ / 2, 512, JAC_SMEM>>>(V, out);
}